// round 4
// baseline (speedup 1.0000x reference)
#include <cuda_runtime.h>
#include <math.h>

#define XS 540
#define YS 540
#define BATCH 4
#define NBOX 64
#define TILE_X 128     // 32 float4 columns
#define TILE_Y 32
#define TXN 5          // ceil(540/128)
#define TYN 17         // ceil(540/32)
#define NBLOCKS (TXN*TYN*BATCH)
#define FIXSCALE 67108864.0   // 2^26

__device__ unsigned long long g_acc[BATCH][3];
__device__ unsigned int g_done;

struct BoxC { float cx, cy, c, s, hw, hl, hv; };

__global__ void __launch_bounds__(256)
hm_loss_fused_kernel(const float* __restrict__ logits,
                     const float* __restrict__ boxes,
                     const float* __restrict__ hm,
                     float* __restrict__ out)
{
    __shared__ BoxC  bc[NBOX];
    __shared__ unsigned int sm_mask[2];
    __shared__ float w0[8], w1[8], w2[8];

    const int b    = blockIdx.z;
    const int tid  = threadIdx.x;
    const int lane = tid & 31;
    const int wrp  = tid >> 5;

    // ---- pixel prefetch (issued before the box barrier; independent of boxes) ----
    const int x4 = blockIdx.x * TILE_X + lane * 4;          // aligned float4 start
    const int yb = blockIdx.y * TILE_Y + wrp;               // rows yb + 8k
    const bool xok = (x4 + 3 < XS);

    float4 lx4[4], lh4[4];
    bool yok[4];
    #pragma unroll
    for (int k = 0; k < 4; k++) {
        const int y = yb + 8 * k;
        yok[k] = xok && (y < YS);
        if (yok[k]) {
            const int idx = (b * YS + y) * XS + x4;
            lx4[k] = *reinterpret_cast<const float4*>(logits + idx);
            lh4[k] = *reinterpret_cast<const float4*>(hm + idx);
        }
    }

    // ---- box processing: warps 0,1 read boxes straight from gmem, cull, ballot ----
    if (tid < NBOX) {
        const float* p = boxes + (b * NBOX + tid) * 7;
        float p0 = p[0], p1 = p[1], p3 = p[3], p4 = p[4], p5 = p[5], p6 = p[6];
        BoxC v;
        v.cx = (p0 + 54.0f) * 5.0f;
        v.cy = (p1 + 54.0f) * 5.0f;
        v.hw = p3 * 2.5f;
        v.hl = p4 * 2.5f;
        float sn, cn;
        __sincosf(p6, &sn, &cn);
        v.c  = cn;           // cos(-theta)
        v.s  = -sn;          // sin(-theta)
        v.hv = p5 * 0.2f;
        bc[tid] = v;

        float ex = fabsf(v.c) * v.hw + fabsf(v.s) * v.hl;
        float ey = fabsf(v.s) * v.hw + fabsf(v.c) * v.hl;
        float tx0 = (float)(blockIdx.x * TILE_X);
        float ty0 = (float)(blockIdx.y * TILE_Y);
        bool hit = (v.cx - ex <= tx0 + (float)(TILE_X - 1)) && (v.cx + ex >= tx0) &&
                   (v.cy - ey <= ty0 + (float)(TILE_Y - 1)) && (v.cy + ey >= ty0);
        unsigned int m = __ballot_sync(0xffffffffu, hit);
        if (lane == 0) sm_mask[wrp] = m;
    }
    __syncthreads();

    const unsigned int m0 = sm_mask[0];
    const unsigned int m1 = sm_mask[1];

    float sv = 0.0f, sb = 0.0f, sf = 0.0f;

    #pragma unroll
    for (int k = 0; k < 4; k++) {
        if (!yok[k]) continue;
        const float fy = (float)(yb + 8 * k);
        const float* xvp = &lx4[k].x;
        const float* hhp = &lh4[k].x;

        #pragma unroll
        for (int j = 0; j < 4; j++) {
            const float fx = (float)(x4 + j);

            // last box wins: walk ballots high index -> low, first hit wins
            float gt = 0.0f;
            unsigned int mm = m1;
            int base = 32;
            #pragma unroll 1
            for (;;) {
                if (mm == 0u) {
                    if (base == 0) break;
                    mm = m0; base = 0;
                    if (mm == 0u) break;
                    continue;
                }
                const int bit = 31 - __clz(mm);
                mm &= ~(1u << bit);
                const BoxC v = bc[base + bit];
                const float dx = fx - v.cx;
                const float dy = fy - v.cy;
                const float lx = dx * v.c - dy * v.s;
                const float ly = dx * v.s + dy * v.c;
                if (fabsf(lx) <= v.hw && fabsf(ly) <= v.hl) { gt = v.hv; break; }
            }

            const float xl = xvp[j];
            const bool pos = (gt > 0.0f);
            if (pos || (hhp[j] > 0.0f)) {
                const float weight = pos ? 5.0f : 0.1f;
                const float e  = __expf(-fabsf(xl));
                const float d  = 1.0f + e;
                const float bce = fmaxf(xl, 0.0f) - xl * gt + __logf(d);
                const float rd = __fdividef(1.0f, d);
                const float p  = (xl >= 0.0f) ? rd : e * rd;     // sigmoid
                const float u  = fmaf(p, 1.0f - 2.0f * gt, gt);  // 1 - p_t
                const float aw = 0.75f - 0.5f * gt;
                sv += 1.0f;
                sb += weight * bce;
                sf += u * u * aw * weight * bce;
            }
        }
    }

    // ---- deterministic reduction ----
    #pragma unroll
    for (int st = 16; st > 0; st >>= 1) {
        sv += __shfl_xor_sync(0xffffffffu, sv, st);
        sb += __shfl_xor_sync(0xffffffffu, sb, st);
        sf += __shfl_xor_sync(0xffffffffu, sf, st);
    }
    if (lane == 0) { w0[wrp] = sv; w1[wrp] = sb; w2[wrp] = sf; }
    __syncthreads();

    if (tid == 0) {
        float t0 = 0.0f, t1 = 0.0f, t2 = 0.0f;
        #pragma unroll
        for (int i = 0; i < 8; i++) { t0 += w0[i]; t1 += w1[i]; t2 += w2[i]; }

        atomicAdd(&g_acc[b][0], (unsigned long long)(t0 + 0.5f));
        atomicAdd(&g_acc[b][1], (unsigned long long)llrint((double)t1 * FIXSCALE));
        atomicAdd(&g_acc[b][2], (unsigned long long)llrint((double)t2 * FIXSCALE));
        __threadfence();

        unsigned int ticket = atomicAdd(&g_done, 1u);
        if (ticket == NBLOCKS - 1) {
            float total = 0.0f, ns = 0.0f;
            #pragma unroll
            for (int bb = 0; bb < BATCH; bb++) {
                double cnt = (double)g_acc[bb][0];
                if (cnt > 0.0) {
                    double s1 = (double)g_acc[bb][1] / FIXSCALE;
                    double s2 = (double)g_acc[bb][2] / FIXSCALE;
                    total += (float)(0.5 * (s1 + s2) / fmax(cnt, 1.0));
                    ns += 1.0f;
                }
            }
            out[0] = (ns > 0.0f) ? (total / fmaxf(ns, 1.0f)) : total;
            #pragma unroll
            for (int bb = 0; bb < BATCH; bb++) {
                g_acc[bb][0] = 0ull; g_acc[bb][1] = 0ull; g_acc[bb][2] = 0ull;
            }
            __threadfence();
            g_done = 0u;
        }
    }
}

extern "C" void kernel_launch(void* const* d_in, const int* in_sizes, int n_in,
                              void* d_out, int out_size)
{
    const float* arrs[3] = { (const float*)d_in[0],
                             (const float*)d_in[1],
                             (const float*)d_in[2] };
    const float* logits = arrs[0];
    const float* boxes  = arrs[1];
    const float* hmap   = arrs[2];
    if (n_in >= 3) {
        int bi = -1;
        for (int i = 0; i < 3; i++)
            if (in_sizes[i] == BATCH * NBOX * 7) { bi = i; break; }
        if (bi >= 0) {
            boxes = arrs[bi];
            int o0 = -1, o1 = -1;
            for (int i = 0; i < 3; i++) {
                if (i == bi) continue;
                if (o0 < 0) o0 = i; else o1 = i;
            }
            logits = arrs[o0];
            hmap   = arrs[o1];
        }
    }

    dim3 block(256, 1, 1);
    dim3 grid(TXN, TYN, BATCH);
    hm_loss_fused_kernel<<<grid, block>>>(logits, boxes, hmap, (float*)d_out);
}

// round 5
// speedup vs baseline: 1.9516x; 1.9516x over previous
#include <cuda_runtime.h>
#include <math.h>

#define XS 540
#define YS 540
#define BATCH 4
#define NBOX 64
#define TILE 32
#define TXN 17
#define TYN 17
#define NBLOCKS (TXN*TYN*BATCH)
#define FIXSCALE 67108864.0   // 2^26

__device__ unsigned long long g_acc[BATCH][3];
__device__ unsigned int g_done;

struct BoxC { float cx, cy, c, s, hw, hl, hv; };

__global__ void __launch_bounds__(256)
hm_loss_fused_kernel(const float* __restrict__ logits,
                     const float* __restrict__ boxes,
                     const float* __restrict__ hm,
                     float* __restrict__ out)
{
    __shared__ BoxC bc[NBOX];
    __shared__ unsigned int sm_mask[2];
    __shared__ float w0[8], w1[8], w2[8];

    const int b    = blockIdx.z;
    const int tid  = threadIdx.x;
    const int lane = tid & 31;
    const int wrp  = tid >> 5;

    // ---- pixel prefetch: thread = 4 contiguous x px in one row ----
    const int x4 = blockIdx.x * TILE + (lane & 7) * 4;   // aligned (540 % 4 == 0)
    const int y  = blockIdx.y * TILE + (tid >> 3);
    const bool ok = (x4 + 3 < XS) && (y < YS);

    float4 xl4, hh4;
    if (ok) {
        const int idx = (b * YS + y) * XS + x4;
        xl4 = *reinterpret_cast<const float4*>(logits + idx);
        hh4 = *reinterpret_cast<const float4*>(hm + idx);
    }

    // ---- boxes: warps 0,1 read gmem directly, transform, cull, ballot ----
    if (tid < NBOX) {
        const float* p = boxes + (b * NBOX + tid) * 7;
        BoxC v;
        v.cx = (p[0] + 54.0f) * 5.0f;
        v.cy = (p[1] + 54.0f) * 5.0f;
        v.hw = p[3] * 2.5f;
        v.hl = p[4] * 2.5f;
        float sn, cn;
        __sincosf(p[6], &sn, &cn);
        v.c  = cn;          // cos(-theta)
        v.s  = -sn;         // sin(-theta)
        v.hv = p[5] * 0.2f;
        bc[tid] = v;

        const float ex = fabsf(v.c) * v.hw + fabsf(v.s) * v.hl;
        const float ey = fabsf(v.s) * v.hw + fabsf(v.c) * v.hl;
        const float tx0 = (float)(blockIdx.x * TILE);
        const float ty0 = (float)(blockIdx.y * TILE);
        const bool hit = (v.cx - ex <= tx0 + (float)(TILE - 1)) && (v.cx + ex >= tx0) &&
                         (v.cy - ey <= ty0 + (float)(TILE - 1)) && (v.cy + ey >= ty0);
        const unsigned int m = __ballot_sync(0xffffffffu, hit);
        if (lane == 0) sm_mask[wrp] = m;
    }
    __syncthreads();

    unsigned long long mask =
        ((unsigned long long)sm_mask[1] << 32) | (unsigned long long)sm_mask[0];

    float sv = 0.0f, sb = 0.0f, sf = 0.0f;

    if (ok) {
        const float fx0 = (float)x4;
        const float fy  = (float)y;

        // rasterize 4 px: scan boxes high->low, sticky first-hit (= last box wins)
        float gt[4] = {0.f, 0.f, 0.f, 0.f};
        bool fnd[4] = {false, false, false, false};
        unsigned long long mm = mask;
        while (mm) {
            const int i = 63 - __clzll(mm);
            mm ^= (1ull << i);
            const BoxC v = bc[i];
            const float dx = fx0 - v.cx;
            const float dy = fy - v.cy;
            float lx = dx * v.c - dy * v.s;
            float ly = dx * v.s + dy * v.c;
            #pragma unroll
            for (int j = 0; j < 4; j++) {
                const bool inside = (fabsf(lx) <= v.hw) && (fabsf(ly) <= v.hl);
                if (inside && !fnd[j]) { gt[j] = v.hv; fnd[j] = true; }
                lx += v.c;
                ly += v.s;
            }
        }

        const float* xvp = &xl4.x;
        const float* hhp = &hh4.x;
        #pragma unroll
        for (int j = 0; j < 4; j++) {
            const float g = gt[j];
            const bool pos = (g > 0.0f);
            if (pos || (hhp[j] > 0.0f)) {
                const float xl = xvp[j];
                const float weight = pos ? 5.0f : 0.1f;
                const float e  = __expf(-fabsf(xl));
                const float d  = 1.0f + e;
                const float bce = fmaxf(xl, 0.0f) - xl * g + __logf(d);
                const float rd = __fdividef(1.0f, d);
                const float p  = (xl >= 0.0f) ? rd : e * rd;    // sigmoid
                const float u  = fmaf(p, 1.0f - 2.0f * g, g);   // 1 - p_t
                const float aw = 0.75f - 0.5f * g;
                sv += 1.0f;
                sb += weight * bce;
                sf += u * u * aw * weight * bce;
            }
        }
    }

    // ---- deterministic reduction ----
    #pragma unroll
    for (int st = 16; st > 0; st >>= 1) {
        sv += __shfl_xor_sync(0xffffffffu, sv, st);
        sb += __shfl_xor_sync(0xffffffffu, sb, st);
        sf += __shfl_xor_sync(0xffffffffu, sf, st);
    }
    if (lane == 0) { w0[wrp] = sv; w1[wrp] = sb; w2[wrp] = sf; }
    __syncthreads();

    if (tid == 0) {
        float t0 = 0.0f, t1 = 0.0f, t2 = 0.0f;
        #pragma unroll
        for (int i = 0; i < 8; i++) { t0 += w0[i]; t1 += w1[i]; t2 += w2[i]; }

        atomicAdd(&g_acc[b][0], (unsigned long long)(t0 + 0.5f));
        atomicAdd(&g_acc[b][1], (unsigned long long)llrint((double)t1 * FIXSCALE));
        atomicAdd(&g_acc[b][2], (unsigned long long)llrint((double)t2 * FIXSCALE));
        __threadfence();

        const unsigned int ticket = atomicAdd(&g_done, 1u);
        if (ticket == NBLOCKS - 1) {
            float total = 0.0f, ns = 0.0f;
            #pragma unroll
            for (int bb = 0; bb < BATCH; bb++) {
                const double cnt = (double)g_acc[bb][0];
                if (cnt > 0.0) {
                    const double s1 = (double)g_acc[bb][1] / FIXSCALE;
                    const double s2 = (double)g_acc[bb][2] / FIXSCALE;
                    total += (float)(0.5 * (s1 + s2) / fmax(cnt, 1.0));
                    ns += 1.0f;
                }
            }
            out[0] = (ns > 0.0f) ? (total / fmaxf(ns, 1.0f)) : total;
            #pragma unroll
            for (int bb = 0; bb < BATCH; bb++) {
                g_acc[bb][0] = 0ull; g_acc[bb][1] = 0ull; g_acc[bb][2] = 0ull;
            }
            __threadfence();
            g_done = 0u;
        }
    }
}

extern "C" void kernel_launch(void* const* d_in, const int* in_sizes, int n_in,
                              void* d_out, int out_size)
{
    const float* arrs[3] = { (const float*)d_in[0],
                             (const float*)d_in[1],
                             (const float*)d_in[2] };
    const float* logits = arrs[0];
    const float* boxes  = arrs[1];
    const float* hmap   = arrs[2];
    if (n_in >= 3) {
        int bi = -1;
        for (int i = 0; i < 3; i++)
            if (in_sizes[i] == BATCH * NBOX * 7) { bi = i; break; }
        if (bi >= 0) {
            boxes = arrs[bi];
            int o0 = -1, o1 = -1;
            for (int i = 0; i < 3; i++) {
                if (i == bi) continue;
                if (o0 < 0) o0 = i; else o1 = i;
            }
            logits = arrs[o0];
            hmap   = arrs[o1];
        }
    }

    dim3 block(256, 1, 1);
    dim3 grid(TXN, TYN, BATCH);
    hm_loss_fused_kernel<<<grid, block>>>(logits, boxes, hmap, (float*)d_out);
}

// round 6
// speedup vs baseline: 2.1228x; 1.0877x over previous
#include <cuda_runtime.h>
#include <math.h>

#define XS 540
#define YS 540
#define BATCH 4
#define NBOX 64
#define TILE 32
#define TXN 17
#define TYN 17
#define NBLOCKS (TXN*TYN*BATCH)
#define FIXSCALE 67108864.0   // 2^26

// per batch: [0]=valid count (int), [1]=combined loss * 2^26
__device__ unsigned long long g_acc[BATCH][2];
__device__ unsigned int g_done;

struct BoxC { float cx, cy, c, s, hw, hl, hv; };

__global__ void __launch_bounds__(256)
hm_loss_fused_kernel(const float* __restrict__ logits,
                     const float* __restrict__ boxes,
                     const float* __restrict__ hm,
                     float* __restrict__ out)
{
    __shared__ BoxC bc[NBOX];
    __shared__ unsigned int sm_mask[2];
    __shared__ float ws[8];
    __shared__ int   wc[8];

    const int b    = blockIdx.z;
    const int tid  = threadIdx.x;
    const int lane = tid & 31;
    const int wrp  = tid >> 5;

    // ---- pixel prefetch: thread = 4 contiguous x px in one row ----
    const int x4 = blockIdx.x * TILE + (lane & 7) * 4;
    const int y  = blockIdx.y * TILE + (tid >> 3);
    const bool ok = (x4 + 3 < XS) && (y < YS);

    float4 xl4, hh4;
    if (ok) {
        const int idx = (b * YS + y) * XS + x4;
        xl4 = *reinterpret_cast<const float4*>(logits + idx);
        hh4 = *reinterpret_cast<const float4*>(hm + idx);
    }

    // ---- boxes: warps 0,1 read gmem directly, transform, cull, ballot ----
    if (tid < NBOX) {
        const float* p = boxes + (b * NBOX + tid) * 7;
        BoxC v;
        v.cx = (p[0] + 54.0f) * 5.0f;
        v.cy = (p[1] + 54.0f) * 5.0f;
        v.hw = p[3] * 2.5f;
        v.hl = p[4] * 2.5f;
        float sn, cn;
        __sincosf(p[6], &sn, &cn);
        v.c  = cn;          // cos(-theta)
        v.s  = -sn;         // sin(-theta)
        v.hv = p[5] * 0.2f;
        bc[tid] = v;

        const float ex = fabsf(v.c) * v.hw + fabsf(v.s) * v.hl;
        const float ey = fabsf(v.s) * v.hw + fabsf(v.c) * v.hl;
        const float tx0 = (float)(blockIdx.x * TILE);
        const float ty0 = (float)(blockIdx.y * TILE);
        const bool hit = (v.cx - ex <= tx0 + (float)(TILE - 1)) && (v.cx + ex >= tx0) &&
                         (v.cy - ey <= ty0 + (float)(TILE - 1)) && (v.cy + ey >= ty0);
        const unsigned int m = __ballot_sync(0xffffffffu, hit);
        if (lane == 0) sm_mask[wrp] = m;
    }
    __syncthreads();

    const unsigned long long mask =
        ((unsigned long long)sm_mask[1] << 32) | (unsigned long long)sm_mask[0];

    float gt[4] = {0.f, 0.f, 0.f, 0.f};
    if (ok) {
        const float fx0 = (float)x4;
        const float fy  = (float)y;
        bool fnd[4] = {false, false, false, false};
        unsigned long long mm = mask;
        while (mm) {
            const int i = 63 - __clzll(mm);
            mm ^= (1ull << i);
            const BoxC v = bc[i];
            const float dx = fx0 - v.cx;
            const float dy = fy - v.cy;
            float lx = dx * v.c - dy * v.s;
            float ly = dx * v.s + dy * v.c;
            #pragma unroll
            for (int j = 0; j < 4; j++) {
                const bool inside = (fabsf(lx) <= v.hw) && (fabsf(ly) <= v.hl);
                if (inside && !fnd[j]) { gt[j] = v.hv; fnd[j] = true; }
                lx += v.c;
                ly += v.s;
            }
        }
    }

    // ---- loss: single combined accumulator + integer valid count ----
    float sc = 0.0f;
    int   cnt = 0;
    const float* xvp = &xl4.x;
    const float* hhp = &hh4.x;
    #pragma unroll
    for (int j = 0; j < 4; j++) {
        const float g = gt[j];
        const bool pos = (g > 0.0f);
        const bool valid = ok && (pos || (hhp[j] > 0.0f));
        const unsigned int vb = __ballot_sync(0xffffffffu, valid);
        if (lane == 0) cnt += __popc(vb);
        if (valid) {
            const float xl = xvp[j];
            const float weight = pos ? 5.0f : 0.1f;
            const float e  = __expf(-fabsf(xl));
            const float d  = 1.0f + e;
            const float bce = fmaxf(xl, 0.0f) - xl * g + __logf(d);
            const float rd = __fdividef(1.0f, d);
            const float p  = (xl >= 0.0f) ? rd : e * rd;    // sigmoid
            const float u  = fmaf(p, 1.0f - 2.0f * g, g);   // 1 - p_t
            const float aw = 0.75f - 0.5f * g;
            // combined = weight*bce*(1 + u*u*aw)  == bce_term + focal_term
            sc += weight * bce * fmaf(u * u, aw, 1.0f);
        }
    }

    // warp reduce the single float
    #pragma unroll
    for (int st = 16; st > 0; st >>= 1)
        sc += __shfl_xor_sync(0xffffffffu, sc, st);
    if (lane == 0) { ws[wrp] = sc; wc[wrp] = cnt; }
    __syncthreads();

    if (tid == 0) {
        float t1 = 0.0f; int t0 = 0;
        #pragma unroll
        for (int i = 0; i < 8; i++) { t0 += wc[i]; t1 += ws[i]; }

        atomicAdd(&g_acc[b][0], (unsigned long long)t0);
        atomicAdd(&g_acc[b][1], (unsigned long long)llrint((double)t1 * FIXSCALE));
        __threadfence();

        const unsigned int ticket = atomicAdd(&g_done, 1u);
        if (ticket == NBLOCKS - 1) {
            float total = 0.0f, ns = 0.0f;
            #pragma unroll
            for (int bb = 0; bb < BATCH; bb++) {
                const double cnt_b = (double)g_acc[bb][0];
                if (cnt_b > 0.0) {
                    const double s = (double)g_acc[bb][1] / FIXSCALE;
                    total += (float)(0.5 * s / fmax(cnt_b, 1.0));
                    ns += 1.0f;
                }
            }
            out[0] = (ns > 0.0f) ? (total / fmaxf(ns, 1.0f)) : total;
            #pragma unroll
            for (int bb = 0; bb < BATCH; bb++) {
                g_acc[bb][0] = 0ull; g_acc[bb][1] = 0ull;
            }
            __threadfence();
            g_done = 0u;
        }
    }
}

extern "C" void kernel_launch(void* const* d_in, const int* in_sizes, int n_in,
                              void* d_out, int out_size)
{
    const float* arrs[3] = { (const float*)d_in[0],
                             (const float*)d_in[1],
                             (const float*)d_in[2] };
    const float* logits = arrs[0];
    const float* boxes  = arrs[1];
    const float* hmap   = arrs[2];
    if (n_in >= 3) {
        int bi = -1;
        for (int i = 0; i < 3; i++)
            if (in_sizes[i] == BATCH * NBOX * 7) { bi = i; break; }
        if (bi >= 0) {
            boxes = arrs[bi];
            int o0 = -1, o1 = -1;
            for (int i = 0; i < 3; i++) {
                if (i == bi) continue;
                if (o0 < 0) o0 = i; else o1 = i;
            }
            logits = arrs[o0];
            hmap   = arrs[o1];
        }
    }

    dim3 block(256, 1, 1);
    dim3 grid(TXN, TYN, BATCH);
    hm_loss_fused_kernel<<<grid, block>>>(logits, boxes, hmap, (float*)d_out);
}